// round 7
// baseline (speedup 1.0000x reference)
#include <cuda_runtime.h>

#define N_NODES 100000
#define N_EDGES 1600000
#define HIDDEN  128
#define OUT_DIM 400

// Scratch (__device__ globals; allocation-free rule)
__device__ float2 d_vd[N_NODES];    // {v accumulation, dinv}
__device__ float  d_deg[N_NODES];   // in-degree (real edges only)
__device__ float  d_a[N_NODES];     // dinv * x
__device__ float  d_u[N_NODES];     // sum over out-edges of dinv[col]
__device__ float  d_g[HIDDEN];      // sum_i t[i] * relu(s[i]*W1 + b1)
__device__ unsigned int d_done;     // last-block-done ticket

// 8B vector atomic: {v,dinv} += {addv, 0}; returns old dinv (element-wise
// atomic; dinv>0 so the +0.0 lane is an exact read).
__device__ __forceinline__ float atomv2_add_ret_dinv(float2* p, float addv) {
    float ox, oy;
    asm volatile("atom.global.add.v2.f32 {%0,%1}, [%2], {%3,%4};"
                 : "=f"(ox), "=f"(oy)
                 : "l"(p), "f"(addv), "f"(0.0f)
                 : "memory");
    return oy;
}

// ---------------------------------------------------------------------------
// Pass 0: zero deg + ticket
__global__ void k_zero() {
    int i = blockIdx.x * blockDim.x + threadIdx.x;
    if (i < N_NODES) d_deg[i] = 0.0f;
    if (i == 0) d_done = 0u;
}

// Pass 1: in-degree histogram over destinations. 4 edges/thread (int4).
__global__ void k_deg(const int* __restrict__ col) {
    int i = blockIdx.x * blockDim.x + threadIdx.x;
    if (i < N_EDGES / 4) {
        int4 c = ((const int4*)col)[i];
        atomicAdd(&d_deg[c.x], 1.0f);
        atomicAdd(&d_deg[c.y], 1.0f);
        atomicAdd(&d_deg[c.z], 1.0f);
        atomicAdd(&d_deg[c.w], 1.0f);
    }
}

// Pass 2: dinv = rsqrt(deg+1); vd = {0, dinv}; a = dinv*x; zero u and g here
// (u, g are first consumed only after this kernel).
__global__ void k_prep(const float* __restrict__ x) {
    int i = blockIdx.x * blockDim.x + threadIdx.x;
    if (i < N_NODES) {
        float dv = rsqrtf(d_deg[i] + 1.0f);
        d_vd[i] = make_float2(0.0f, dv);
        d_a[i]  = dv * x[i];
        d_u[i]  = 0.0f;
    }
    if (i < HIDDEN) d_g[i] = 0.0f;
}

// Pass 3: main edge pass, 3 random lane-ops per edge, 4 edges/thread:
//   a_r = a[row]                       (gather)
//   {v[col],dinv[col]} += {a_r, 0}     (v2 atomic, returns dinv[col])
//   u[row] += dinv[col]                (red)
__global__ void k_edges(const int* __restrict__ row,
                        const int* __restrict__ col) {
    int i = blockIdx.x * blockDim.x + threadIdx.x;
    if (i >= N_EDGES / 4) return;
    int4 r = ((const int4*)row)[i];
    int4 c = ((const int4*)col)[i];

    float a0 = __ldg(&d_a[r.x]), a1 = __ldg(&d_a[r.y]);
    float a2 = __ldg(&d_a[r.z]), a3 = __ldg(&d_a[r.w]);

    float dc0 = atomv2_add_ret_dinv(&d_vd[c.x], a0);
    float dc1 = atomv2_add_ret_dinv(&d_vd[c.y], a1);
    float dc2 = atomv2_add_ret_dinv(&d_vd[c.z], a2);
    float dc3 = atomv2_add_ret_dinv(&d_vd[c.w], a3);

    atomicAdd(&d_u[r.x], dc0);
    atomicAdd(&d_u[r.y], dc1);
    atomicAdd(&d_u[r.z], dc2);
    atomicAdd(&d_u[r.w], dc3);
}

// Pass 4 (fused epilogue): finalize s,t on the fly, accumulate
//   g[f] += sum_i t[i] * relu(s[i]*W1[f] + b1[f]),
// then the LAST block to finish computes
//   out[k] = b2[k] + (1/N) * sum_f g[f] * W2[f,k].
__global__ void k_accum_g(const float* __restrict__ x,
                          const float* __restrict__ W1,
                          const float* __restrict__ b1,
                          const float* __restrict__ W2,
                          const float* __restrict__ b2,
                          float* __restrict__ out) {
    __shared__ float ss[128];
    __shared__ float st[128];
    __shared__ unsigned int s_ticket;
    int f = threadIdx.x;
    float w  = W1[f];
    float bb = b1[f];
    float acc = 0.0f;

    for (int base = blockIdx.x * 128; base < N_NODES; base += gridDim.x * 128) {
        int idx = base + f;
        __syncthreads();
        if (idx < N_NODES) {
            float2 vd = d_vd[idx];
            float dv = vd.y;
            ss[f] = dv * (vd.x + dv * x[idx]);
            st[f] = dv * (d_u[idx] + dv);
        } else {
            ss[f] = 0.0f;
            st[f] = 0.0f;
        }
        __syncthreads();
#pragma unroll 16
        for (int j = 0; j < 128; j++) {
            acc += st[j] * fmaxf(fmaf(ss[j], w, bb), 0.0f);
        }
    }
    atomicAdd(&d_g[f], acc);
    __threadfence();
    if (f == 0) s_ticket = atomicAdd(&d_done, 1u);
    __syncthreads();

    if (s_ticket == gridDim.x - 1) {
        // All other blocks' g contributions are visible (fence + RMW order).
        __threadfence();
        __shared__ float gs[HIDDEN];
        gs[f] = d_g[f];
        __syncthreads();
        for (int k = f; k < OUT_DIM; k += 128) {
            float o = 0.0f;
#pragma unroll 16
            for (int j = 0; j < HIDDEN; j++) {
                o = fmaf(gs[j], W2[j * OUT_DIM + k], o);
            }
            out[k] = b2[k] + o * (1.0f / (float)N_NODES);
        }
    }
}

// ---------------------------------------------------------------------------
extern "C" void kernel_launch(void* const* d_in, const int* in_sizes, int n_in,
                              void* d_out, int out_size) {
    const float* x  = (const float*)d_in[0];        // [N, 1]
    const int*   ei = (const int*)d_in[1];          // [2, E]: row then col
    const float* W1 = (const float*)d_in[2];        // [1, 128]
    const float* b1 = (const float*)d_in[3];        // [128]
    const float* W2 = (const float*)d_in[4];        // [128, 400]
    const float* b2 = (const float*)d_in[5];        // [400]
    float* out = (float*)d_out;                     // [400]

    const int* row = ei;
    const int* col = ei + N_EDGES;

    const int ET = N_EDGES / 4;                     // 400000 threads

    k_zero   <<<(N_NODES + 255) / 256, 256>>>();
    k_deg    <<<(ET + 255) / 256, 256>>>(col);
    k_prep   <<<(N_NODES + 255) / 256, 256>>>(x);
    k_edges  <<<(ET + 255) / 256, 256>>>(row, col);
    k_accum_g<<<304, 128>>>(x, W1, b1, W2, b2, out);
}